// round 1
// baseline (speedup 1.0000x reference)
#include <cuda_runtime.h>

#define DFEAT 64
#define MAXN 100000

// Scratch (device globals — no allocation allowed in kernel_launch)
__device__ float g_sum[(size_t)MAXN * DFEAT];
__device__ float g_deg[MAXN];

// ---------------------------------------------------------------------------
// Kernel 1: zero the aggregation scratch (runs every launch -> deterministic)
// ---------------------------------------------------------------------------
__global__ void zero_scratch(int n) {
    int i = blockIdx.x * blockDim.x + threadIdx.x;
    int total4 = n * (DFEAT / 4);
    if (i < total4) ((float4*)g_sum)[i] = make_float4(0.f, 0.f, 0.f, 0.f);
    if (i < n) g_deg[i] = 0.f;
}

// ---------------------------------------------------------------------------
// Kernel 2: edge scatter-add. 16 lanes per edge, float4 each.
// Vector reduction (red.global.add.v4.f32) quarters the L2 atomic op count.
// ---------------------------------------------------------------------------
__global__ void edge_scatter(const float* __restrict__ h,
                             const int* __restrict__ src,
                             const int* __restrict__ dst,
                             int E) {
    int t = blockIdx.x * blockDim.x + threadIdx.x;
    int e = t >> 4;
    if (e >= E) return;
    int c = t & 15;

    int s = __ldg(src + e);
    int d = __ldg(dst + e);

    float4 v = __ldg((const float4*)(h + (size_t)s * DFEAT) + c);
    float* p = g_sum + (size_t)d * DFEAT + c * 4;
    asm volatile("red.global.add.v4.f32 [%0], {%1, %2, %3, %4};"
                 :: "l"(p), "f"(v.x), "f"(v.y), "f"(v.z), "f"(v.w)
                 : "memory");
    if (c == 0) atomicAdd(&g_deg[d], 1.0f);
}

// ---------------------------------------------------------------------------
// Kernel 3: node update.
//   c = sum/max(deg,1); bundle = [h,c] @ W^T + b; L2 normalize; relu;
//   keep h where deg==0; residual add.
// One warp processes 8 nodes per iteration; W cached in shared with
// row stride 132 floats (stride % 32 == 4 -> conflict-free LDS.128 across
// 8-lane groups). Lane L owns output columns L and L+32.
// ---------------------------------------------------------------------------
#define WPB 4        // warps per block
#define NPW 8        // nodes per warp per iteration
#define WSTRIDE 132  // padded row stride for W in shared (floats)

__global__ void node_update(const float* __restrict__ h,
                            const float* __restrict__ W,
                            const float* __restrict__ b,
                            float* __restrict__ out,
                            int n) {
    extern __shared__ float smem[];
    float* Ws = smem;                       // 64 * 132 floats
    float* bs = Ws + 64 * WSTRIDE;          // 64 floats
    float* hc = bs + 64;                    // WPB * NPW * 128 floats

    int tid = threadIdx.x;

    // Stage W (row-major [64][128]) into padded shared.
    for (int i = tid; i < 64 * 128; i += blockDim.x) {
        int r = i >> 7, c = i & 127;
        Ws[r * WSTRIDE + c] = W[i];
    }
    if (tid < 64) bs[tid] = b[tid];
    __syncthreads();

    int lane = tid & 31;
    int warp = tid >> 5;
    float* hcw = hc + warp * (NPW * 128);

    int warpGlobal = blockIdx.x * WPB + warp;
    int numWarps = gridDim.x * WPB;

    const float4* w0p = (const float4*)(Ws + lane * WSTRIDE);
    const float4* w1p = (const float4*)(Ws + lane * WSTRIDE + 64);
    const float4* w2p = (const float4*)(Ws + (lane + 32) * WSTRIDE);
    const float4* w3p = (const float4*)(Ws + (lane + 32) * WSTRIDE + 64);

    for (int base = warpGlobal * NPW; base < n; base += numWarps * NPW) {
        int cnt = n - base; if (cnt > NPW) cnt = NPW;
        float degs[NPW];

        // Stage h and c=sum/max(deg,1) for 8 nodes into shared.
        #pragma unroll
        for (int j = 0; j < NPW; j++) {
            int node = base + j;
            if (j < cnt) {
                float2 hv = *(const float2*)(h + (size_t)node * 64 + lane * 2);
                float2 sv = *(const float2*)(g_sum + (size_t)node * 64 + lane * 2);
                float dg = g_deg[node];
                degs[j] = dg;
                float inv = 1.0f / fmaxf(dg, 1.0f);
                ((float2*)(hcw + j * 128))[lane] = hv;
                ((float2*)(hcw + j * 128 + 64))[lane] = make_float2(sv.x * inv, sv.y * inv);
            } else {
                degs[j] = 0.f;
                ((float2*)(hcw + j * 128))[lane] = make_float2(0.f, 0.f);
                ((float2*)(hcw + j * 128 + 64))[lane] = make_float2(0.f, 0.f);
            }
        }
        __syncwarp();

        float acc0[NPW], acc1[NPW];
        #pragma unroll
        for (int j = 0; j < NPW; j++) { acc0[j] = bs[lane]; acc1[j] = bs[lane + 32]; }

        // Main GEMM loop: 16 k4-steps over the 128-dim concat input.
        #pragma unroll
        for (int k4 = 0; k4 < 16; k4++) {
            float4 w0 = w0p[k4];
            float4 w1 = w1p[k4];
            float4 w2 = w2p[k4];
            float4 w3 = w3p[k4];
            #pragma unroll
            for (int j = 0; j < NPW; j++) {
                float4 hk = *(const float4*)(hcw + j * 128 + k4 * 4);
                float4 ck = *(const float4*)(hcw + j * 128 + 64 + k4 * 4);
                acc0[j] += w0.x * hk.x + w0.y * hk.y + w0.z * hk.z + w0.w * hk.w;
                acc0[j] += w1.x * ck.x + w1.y * ck.y + w1.z * ck.z + w1.w * ck.w;
                acc1[j] += w2.x * hk.x + w2.y * hk.y + w2.z * hk.z + w2.w * hk.w;
                acc1[j] += w3.x * ck.x + w3.y * ck.y + w3.z * ck.z + w3.w * ck.w;
            }
        }

        // Epilogue: L2 normalize over 64 outputs, relu, deg mask, residual.
        #pragma unroll
        for (int j = 0; j < NPW; j++) {
            float ss = acc0[j] * acc0[j] + acc1[j] * acc1[j];
            #pragma unroll
            for (int o = 16; o > 0; o >>= 1)
                ss += __shfl_xor_sync(0xFFFFFFFFu, ss, o);
            float inv = 1.0f / fmaxf(sqrtf(ss), 1e-12f);
            if (j < cnt) {
                int node = base + j;
                float h0 = hcw[j * 128 + lane];
                float h1 = hcw[j * 128 + lane + 32];
                bool has = degs[j] > 0.f;
                float u0 = has ? fmaxf(acc0[j] * inv, 0.f) : h0;
                float u1 = has ? fmaxf(acc1[j] * inv, 0.f) : h1;
                out[(size_t)node * 64 + lane] = h0 + u0;
                out[(size_t)node * 64 + lane + 32] = h1 + u1;
            }
        }
        __syncwarp();
    }
}

// ---------------------------------------------------------------------------
extern "C" void kernel_launch(void* const* d_in, const int* in_sizes, int n_in,
                              void* d_out, int out_size) {
    const float* h   = (const float*)d_in[0];  // [N, 64]
    const float* W   = (const float*)d_in[1];  // [64, 128]
    const float* b   = (const float*)d_in[2];  // [64]
    const int*   src = (const int*)d_in[3];    // [E]
    const int*   dst = (const int*)d_in[4];    // [E]
    float* out = (float*)d_out;

    int n = in_sizes[0] / DFEAT;
    int E = in_sizes[3];

    // 1. zero scratch
    {
        int total = n * (DFEAT / 4);  // covers g_deg too since n < total
        int blocks = (total + 255) / 256;
        zero_scratch<<<blocks, 256>>>(n);
    }

    // 2. edge scatter
    {
        long long threads = (long long)E * 16;
        int blocks = (int)((threads + 255) / 256);
        edge_scatter<<<blocks, 256>>>(h, src, dst, E);
    }

    // 3. node update
    {
        int smemBytes = (64 * WSTRIDE + 64 + WPB * NPW * 128) * (int)sizeof(float);
        cudaFuncSetAttribute(node_update, cudaFuncAttributeMaxDynamicSharedMemorySize,
                             smemBytes);
        node_update<<<592, WPB * 32, smemBytes>>>(h, W, b, out, n);
    }
}

// round 2
// speedup vs baseline: 1.0382x; 1.0382x over previous
#include <cuda_runtime.h>

#define DFEAT 64
#define MAXN 100000

// Scratch (device globals — no allocation allowed in kernel_launch)
__device__ float g_sum[(size_t)MAXN * DFEAT];
__device__ float g_deg[MAXN];

// ---------------------------------------------------------------------------
// Kernel 1: zero the aggregation scratch (runs every launch -> deterministic)
// ---------------------------------------------------------------------------
__global__ void zero_scratch(int n) {
    int i = blockIdx.x * blockDim.x + threadIdx.x;
    int total4 = n * (DFEAT / 4);
    if (i < total4) ((float4*)g_sum)[i] = make_float4(0.f, 0.f, 0.f, 0.f);
    if (i < n) g_deg[i] = 0.f;
}

// ---------------------------------------------------------------------------
// Kernel 2: edge scatter-add. 16 lanes per edge, float4 each.
// Vector reduction (red.global.add.v4.f32) quarters the L2 atomic op count.
// ---------------------------------------------------------------------------
__global__ void edge_scatter(const float* __restrict__ h,
                             const int* __restrict__ src,
                             const int* __restrict__ dst,
                             int E) {
    int t = blockIdx.x * blockDim.x + threadIdx.x;
    int e = t >> 4;
    if (e >= E) return;
    int c = t & 15;

    int s = __ldg(src + e);
    int d = __ldg(dst + e);

    float4 v = __ldg((const float4*)(h + (size_t)s * DFEAT) + c);
    float* p = g_sum + (size_t)d * DFEAT + c * 4;
    asm volatile("red.global.add.v4.f32 [%0], {%1, %2, %3, %4};"
                 :: "l"(p), "f"(v.x), "f"(v.y), "f"(v.z), "f"(v.w)
                 : "memory");
    if (c == 0) atomicAdd(&g_deg[d], 1.0f);
}

// ---------------------------------------------------------------------------
// Kernel 3: node update.
//   c = sum/max(deg,1); bundle = [h,c] @ W^T + b; L2 normalize; relu;
//   keep h where deg==0; residual add.
// One warp processes 8 nodes per iteration; W cached in shared with
// row stride 132 floats (stride % 32 == 4 -> conflict-free LDS.128 across
// 8-lane groups). Lane L owns output columns L and L+32.
// ---------------------------------------------------------------------------
#define WPB 4        // warps per block
#define NPW 8        // nodes per warp per iteration
#define WSTRIDE 132  // padded row stride for W in shared (floats)

__global__ void node_update(const float* __restrict__ h,
                            const float* __restrict__ W,
                            const float* __restrict__ b,
                            float* __restrict__ out,
                            int n) {
    extern __shared__ float smem[];
    float* Ws = smem;                       // 64 * 132 floats
    float* bs = Ws + 64 * WSTRIDE;          // 64 floats
    float* hc = bs + 64;                    // WPB * NPW * 128 floats

    int tid = threadIdx.x;

    // Stage W (row-major [64][128]) into padded shared.
    for (int i = tid; i < 64 * 128; i += blockDim.x) {
        int r = i >> 7, c = i & 127;
        Ws[r * WSTRIDE + c] = W[i];
    }
    if (tid < 64) bs[tid] = b[tid];
    __syncthreads();

    int lane = tid & 31;
    int warp = tid >> 5;
    float* hcw = hc + warp * (NPW * 128);

    int warpGlobal = blockIdx.x * WPB + warp;
    int numWarps = gridDim.x * WPB;

    const float4* w0p = (const float4*)(Ws + lane * WSTRIDE);
    const float4* w1p = (const float4*)(Ws + lane * WSTRIDE + 64);
    const float4* w2p = (const float4*)(Ws + (lane + 32) * WSTRIDE);
    const float4* w3p = (const float4*)(Ws + (lane + 32) * WSTRIDE + 64);

    for (int base = warpGlobal * NPW; base < n; base += numWarps * NPW) {
        int cnt = n - base; if (cnt > NPW) cnt = NPW;
        float degs[NPW];

        // Stage h and c=sum/max(deg,1) for 8 nodes into shared.
        #pragma unroll
        for (int j = 0; j < NPW; j++) {
            int node = base + j;
            if (j < cnt) {
                float2 hv = *(const float2*)(h + (size_t)node * 64 + lane * 2);
                float2 sv = *(const float2*)(g_sum + (size_t)node * 64 + lane * 2);
                float dg = g_deg[node];
                degs[j] = dg;
                float inv = 1.0f / fmaxf(dg, 1.0f);
                ((float2*)(hcw + j * 128))[lane] = hv;
                ((float2*)(hcw + j * 128 + 64))[lane] = make_float2(sv.x * inv, sv.y * inv);
            } else {
                degs[j] = 0.f;
                ((float2*)(hcw + j * 128))[lane] = make_float2(0.f, 0.f);
                ((float2*)(hcw + j * 128 + 64))[lane] = make_float2(0.f, 0.f);
            }
        }
        __syncwarp();

        float acc0[NPW], acc1[NPW];
        #pragma unroll
        for (int j = 0; j < NPW; j++) { acc0[j] = bs[lane]; acc1[j] = bs[lane + 32]; }

        // Main GEMM loop: 16 k4-steps over the 128-dim concat input.
        #pragma unroll
        for (int k4 = 0; k4 < 16; k4++) {
            float4 w0 = w0p[k4];
            float4 w1 = w1p[k4];
            float4 w2 = w2p[k4];
            float4 w3 = w3p[k4];
            #pragma unroll
            for (int j = 0; j < NPW; j++) {
                float4 hk = *(const float4*)(hcw + j * 128 + k4 * 4);
                float4 ck = *(const float4*)(hcw + j * 128 + 64 + k4 * 4);
                acc0[j] += w0.x * hk.x + w0.y * hk.y + w0.z * hk.z + w0.w * hk.w;
                acc0[j] += w1.x * ck.x + w1.y * ck.y + w1.z * ck.z + w1.w * ck.w;
                acc1[j] += w2.x * hk.x + w2.y * hk.y + w2.z * hk.z + w2.w * hk.w;
                acc1[j] += w3.x * ck.x + w3.y * ck.y + w3.z * ck.z + w3.w * ck.w;
            }
        }

        // Epilogue: L2 normalize over 64 outputs, relu, deg mask, residual.
        #pragma unroll
        for (int j = 0; j < NPW; j++) {
            float ss = acc0[j] * acc0[j] + acc1[j] * acc1[j];
            #pragma unroll
            for (int o = 16; o > 0; o >>= 1)
                ss += __shfl_xor_sync(0xFFFFFFFFu, ss, o);
            float inv = 1.0f / fmaxf(sqrtf(ss), 1e-12f);
            if (j < cnt) {
                int node = base + j;
                float h0 = hcw[j * 128 + lane];
                float h1 = hcw[j * 128 + lane + 32];
                bool has = degs[j] > 0.f;
                float u0 = has ? fmaxf(acc0[j] * inv, 0.f) : h0;
                float u1 = has ? fmaxf(acc1[j] * inv, 0.f) : h1;
                out[(size_t)node * 64 + lane] = h0 + u0;
                out[(size_t)node * 64 + lane + 32] = h1 + u1;
            }
        }
        __syncwarp();
    }
}

// ---------------------------------------------------------------------------
extern "C" void kernel_launch(void* const* d_in, const int* in_sizes, int n_in,
                              void* d_out, int out_size) {
    const float* h   = (const float*)d_in[0];  // [N, 64]
    const float* W   = (const float*)d_in[1];  // [64, 128]
    const float* b   = (const float*)d_in[2];  // [64]
    const int*   src = (const int*)d_in[3];    // [E]
    const int*   dst = (const int*)d_in[4];    // [E]
    float* out = (float*)d_out;

    int n = in_sizes[0] / DFEAT;
    int E = in_sizes[3];

    // 1. zero scratch
    {
        int total = n * (DFEAT / 4);  // covers g_deg too since n < total
        int blocks = (total + 255) / 256;
        zero_scratch<<<blocks, 256>>>(n);
    }

    // 2. edge scatter
    {
        long long threads = (long long)E * 16;
        int blocks = (int)((threads + 255) / 256);
        edge_scatter<<<blocks, 256>>>(h, src, dst, E);
    }

    // 3. node update
    {
        int smemBytes = (64 * WSTRIDE + 64 + WPB * NPW * 128) * (int)sizeof(float);
        cudaFuncSetAttribute(node_update, cudaFuncAttributeMaxDynamicSharedMemorySize,
                             smemBytes);
        node_update<<<592, WPB * 32, smemBytes>>>(h, W, b, out, n);
    }
}